// round 2
// baseline (speedup 1.0000x reference)
#include <cuda_runtime.h>
#include <cstdint>

#define NBATCH 4
#define NA 25200
#define NCLS 80
#define ROWF 85
#define ATTNF 980
#define AR 14
#define NB5 5
#define CONF 0.25f
#define IOUT 0.45f
#define MAXDET 100
#define TOPK 1024
#define HBINS 1024
#define MAXC 2048
#define HW 160
#define OUTROW 25606
#define TILE_A 48

// ---------------- scratch (device globals; no allocations allowed) ----------
__device__ unsigned int       g_hist[NBATCH * HBINS];
__device__ int                g_thrBin[NBATCH];
__device__ int                g_candCnt[NBATCH];
__device__ unsigned long long g_candKey[NBATCH * MAXC];
__device__ unsigned long long g_topKey[NBATCH * TOPK];
__device__ int                g_detAnchor[NBATCH * MAXDET];

// ---------------- init: zero hist/counters every replay ---------------------
__global__ void k_init() {
    int t = blockIdx.x * blockDim.x + threadIdx.x;
    if (t < NBATCH * HBINS) g_hist[t] = 0u;
    if (t < NBATCH) { g_candCnt[t] = 0; g_thrBin[t] = 256; }
}

// ---------------- pass 1: per-batch histogram of scores > CONF --------------
__global__ void k_hist(const float* __restrict__ test) {
    __shared__ float        tile[TILE_A * ROWF];
    __shared__ unsigned int hh[HBINS];
    const int b = blockIdx.y;
    for (int i = threadIdx.x; i < HBINS; i += blockDim.x) hh[i] = 0u;
    const float* tb = test + (size_t)b * NA * ROWF;
    const int ntiles = NA / TILE_A;   // 525 exactly
    for (int tid = blockIdx.x; tid < ntiles; tid += gridDim.x) {
        __syncthreads();
        const float* src = tb + (size_t)tid * TILE_A * ROWF;
        for (int i = threadIdx.x; i < TILE_A * ROWF; i += blockDim.x) tile[i] = src[i];
        __syncthreads();
        for (int k = threadIdx.x; k < TILE_A * NCLS; k += blockDim.x) {
            int a = k / NCLS, c = k - a * NCLS;
            float v = tile[a * ROWF + 5 + c] * tile[a * ROWF + 4];
            if (v > CONF) {
                int bin = (int)(v * 1024.0f); bin = bin > 1023 ? 1023 : bin;
                atomicAdd(&hh[bin], 1u);
            }
        }
    }
    __syncthreads();
    for (int i = threadIdx.x; i < HBINS; i += blockDim.x)
        if (hh[i]) atomicAdd(&g_hist[b * HBINS + i], hh[i]);
}

// ---------------- find the bin whose suffix count first reaches TOPK --------
__global__ void k_thresh() {
    __shared__ unsigned int s[HBINS];
    const int b = blockIdx.x;
    const int t = threadIdx.x;
    s[t] = g_hist[b * HBINS + t];
    __syncthreads();
    for (int off = 1; off < HBINS; off <<= 1) {
        unsigned v = (t + off < HBINS) ? s[t + off] : 0u;
        __syncthreads();
        s[t] += v;
        __syncthreads();
    }
    if (s[t] >= TOPK && (t == HBINS - 1 || s[t + 1] < TOPK)) g_thrBin[b] = t;
}

// ---------------- pass 2: compact candidates (bin >= thr) -------------------
__global__ void k_compact(const float* __restrict__ test) {
    __shared__ float tile[TILE_A * ROWF];
    const int b   = blockIdx.y;
    const int thr = g_thrBin[b];
    const float* tb = test + (size_t)b * NA * ROWF;
    const int ntiles = NA / TILE_A;
    for (int tid = blockIdx.x; tid < ntiles; tid += gridDim.x) {
        __syncthreads();
        const float* src = tb + (size_t)tid * TILE_A * ROWF;
        for (int i = threadIdx.x; i < TILE_A * ROWF; i += blockDim.x) tile[i] = src[i];
        __syncthreads();
        for (int k = threadIdx.x; k < TILE_A * NCLS; k += blockDim.x) {
            int a = k / NCLS, c = k - a * NCLS;
            float v = tile[a * ROWF + 5 + c] * tile[a * ROWF + 4];
            if (v > CONF) {
                int bin = (int)(v * 1024.0f); bin = bin > 1023 ? 1023 : bin;
                if (bin >= thr) {
                    int pos = atomicAdd(&g_candCnt[b], 1);
                    if (pos < MAXC) {
                        unsigned flat = (unsigned)((tid * TILE_A + a) * NCLS + c);
                        g_candKey[b * MAXC + pos] =
                            ((unsigned long long)__float_as_uint(v) << 32) |
                            (unsigned long long)(0xFFFFFFFFu - flat);
                    }
                }
            }
        }
    }
}

// ---------------- bitonic sort 2048 keys desc; emit top 1024 ----------------
__global__ void k_sort() {
    __shared__ unsigned long long s[MAXC];
    const int b = blockIdx.x;
    int cnt = g_candCnt[b]; if (cnt > MAXC) cnt = MAXC;
    for (int i = threadIdx.x; i < MAXC; i += blockDim.x)
        s[i] = (i < cnt) ? g_candKey[b * MAXC + i] : 0x00000000FFFFFFFFull;
    __syncthreads();
    for (int k = 2; k <= MAXC; k <<= 1) {
        for (int j = k >> 1; j > 0; j >>= 1) {
            for (int i = threadIdx.x; i < MAXC; i += blockDim.x) {
                int ixj = i ^ j;
                if (ixj > i) {
                    unsigned long long a = s[i], bb = s[ixj];
                    bool up = (i & k) == 0;
                    if (up ? (a < bb) : (a > bb)) { s[i] = bb; s[ixj] = a; }
                }
            }
            __syncthreads();
        }
    }
    for (int i = threadIdx.x; i < TOPK; i += blockDim.x)
        g_topKey[b * TOPK + i] = s[i];
}

// ---------------- greedy class-aware NMS, writes det headers ----------------
__global__ void k_nms(const float* __restrict__ test, float* __restrict__ out) {
    __shared__ float sbx1[TOPK], sby1[TOPK], sbx2[TOPK], sby2[TOPK], sar[TOPK], sval[TOPK];
    __shared__ int   scls[TOPK], sanc[TOPK];
    __shared__ unsigned int vword[TOPK / 32];
    __shared__ int sj;
    const int b = blockIdx.x;
    const int t = threadIdx.x;

    unsigned long long key = g_topKey[b * TOPK + t];
    float v = __uint_as_float((unsigned)(key >> 32));
    unsigned flat = 0xFFFFFFFFu - (unsigned)(key & 0xFFFFFFFFull);
    bool valid = v > CONF;
    int anc = valid ? (int)(flat / NCLS) : 0;
    int cls = valid ? (int)(flat - (unsigned)anc * NCLS) : 0;

    const float* r = test + ((size_t)b * NA + anc) * ROWF;
    float cx = r[0], cy = r[1], w = r[2], h = r[3];
    float x1 = cx - 0.5f * w, y1 = cy - 0.5f * h;
    float x2 = cx + 0.5f * w, y2 = cy + 0.5f * h;
    sbx1[t] = x1; sby1[t] = y1; sbx2[t] = x2; sby2[t] = y2;
    sar[t] = fmaxf(x2 - x1, 0.f) * fmaxf(y2 - y1, 0.f);
    sval[t] = v; scls[t] = cls; sanc[t] = anc;

    unsigned bal = __ballot_sync(0xFFFFFFFFu, valid);
    if ((t & 31) == 0) vword[t >> 5] = bal;
    __syncthreads();

    for (int det = 0; det < MAXDET; det++) {
        if (t < 32) {
            unsigned m   = vword[t];
            unsigned act = __ballot_sync(0xFFFFFFFFu, m != 0);
            int wsel = act ? (__ffs(act) - 1) : 0;
            unsigned mw = __shfl_sync(0xFFFFFFFFu, m, wsel);
            if (t == 0) sj = act ? (wsel * 32 + __ffs(mw) - 1) : -1;
        }
        __syncthreads();
        int j = sj;
        if (t == 0) {
            size_t ob = (size_t)(b * MAXDET + det) * OUTROW;
            if (j >= 0) {
                out[ob + 0] = sbx1[j]; out[ob + 1] = sby1[j];
                out[ob + 2] = sbx2[j]; out[ob + 3] = sby2[j];
                out[ob + 4] = sval[j]; out[ob + 5] = (float)scls[j];
                g_detAnchor[b * MAXDET + det] = sanc[j];
            } else {
                out[ob+0]=0.f; out[ob+1]=0.f; out[ob+2]=0.f;
                out[ob+3]=0.f; out[ob+4]=0.f; out[ob+5]=0.f;
                g_detAnchor[b * MAXDET + det] = 0;
            }
        }
        bool sup = false;
        if (j >= 0) {
            if (t == j) sup = true;
            else if (cls == scls[j]) {
                float lx = fmaxf(x1, sbx1[j]), ly = fmaxf(y1, sby1[j]);
                float rx = fminf(x2, sbx2[j]), ry = fminf(y2, sby2[j]);
                float iw = fmaxf(rx - lx, 0.f), ih = fmaxf(ry - ly, 0.f);
                float inter = iw * ih;
                float iou = inter / (sar[t] + sar[j] - inter + 1e-9f);
                sup = iou > IOUT;
            }
        }
        unsigned sm = __ballot_sync(0xFFFFFFFFu, sup);
        if ((t & 31) == 0) vword[t >> 5] &= ~sm;
        __syncthreads();
    }
}

// ---------------- mask generation: roi-align + coeff resize + softmax -------
__global__ void k_masks(const float* __restrict__ test,
                        const float* __restrict__ attn,
                        const float* __restrict__ bases,
                        const float* __restrict__ sem,
                        float* __restrict__ out) {
    __shared__ float sA[NB5 * AR * AR];
    __shared__ float sP[4];
    const int b   = blockIdx.z;
    const int det = blockIdx.y;
    const int t   = threadIdx.x;
    const int anc = g_detAnchor[b * MAXDET + det];

    {
        const float* ap = attn + ((size_t)b * NA + anc) * ATTNF;
        for (int i = t; i < NB5 * AR * AR; i += blockDim.x) sA[i] = ap[i];
    }
    if (t == 0) {
        const float* r = test + ((size_t)b * NA + anc) * ROWF;
        float cx = r[0], cy = r[1], w = r[2], h = r[3];
        float bx1 = cx - 0.5f * w, by1 = cy - 0.5f * h;
        float bx2 = cx + 0.5f * w, by2 = cy + 0.5f * h;
        float X1 = bx1 * 0.25f - 0.5f, Y1 = by1 * 0.25f - 0.5f;
        float X2 = bx2 * 0.25f - 0.5f, Y2 = by2 * 0.25f - 0.5f;
        sP[0] = X1; sP[1] = Y1;
        sP[2] = (X2 - X1) / (float)HW;
        sP[3] = (Y2 - Y1) / (float)HW;
    }
    __syncthreads();

    const int lr = t / HW;          // 0..1 (two rows per block-iteration)
    const int px = t - lr * HW;
    const float X1 = sP[0], Y1 = sP[1], DX = sP[2], DY = sP[3];

    // x-side roi-align precompute (fixed per thread)
    float sx = X1 + (px + 0.5f) * DX;
    bool vx = (sx > -1.0f) && (sx < (float)HW);
    float cxc = fminf(fmaxf(sx, 0.0f), (float)(HW - 1));
    float fxl = floorf(cxc);
    int   x0  = (int)fxl;
    int   x1i = min(x0 + 1, HW - 1);
    float fx  = cxc - fxl;

    // x-side coeff resize precompute
    float txc = (px + 0.5f) * ((float)AR / (float)HW) - 0.5f;
    txc = fminf(fmaxf(txc, 0.0f), (float)(AR - 1));
    float ftx = floorf(txc);
    int   cx0 = (int)ftx;
    int   cx1 = min(cx0 + 1, AR - 1);
    float wcx = txc - ftx;

    const float* bp[5];
#pragma unroll
    for (int c = 0; c < 4; c++) bp[c] = bases + ((size_t)(b * 4 + c)) * (HW * HW);
    bp[4] = sem + (size_t)b * (HW * HW);

    const size_t obase = (size_t)(b * MAXDET + det) * OUTROW + 6;

    for (int rp = 0; rp < 8; rp++) {
        int py = blockIdx.x * 16 + rp * 2 + lr;

        float sy = Y1 + (py + 0.5f) * DY;
        bool vy = (sy > -1.0f) && (sy < (float)HW);
        float cyc2 = fminf(fmaxf(sy, 0.0f), (float)(HW - 1));
        float fyl = floorf(cyc2);
        int   y0  = (int)fyl;
        int   y1i = min(y0 + 1, HW - 1);
        float fy  = cyc2 - fyl;

        float tyc = (py + 0.5f) * ((float)AR / (float)HW) - 0.5f;
        tyc = fminf(fmaxf(tyc, 0.0f), (float)(AR - 1));
        float fty = floorf(tyc);
        int   cy0 = (int)fty;
        int   cy1 = min(cy0 + 1, AR - 1);
        float wcy = tyc - fty;

        float co[5];
#pragma unroll
        for (int c = 0; c < 5; c++) {
            const float* A = sA + c * (AR * AR);
            float a00 = A[cy0 * AR + cx0], a01 = A[cy0 * AR + cx1];
            float a10 = A[cy1 * AR + cx0], a11 = A[cy1 * AR + cx1];
            float top = a00 + (a01 - a00) * wcx;
            float bot = a10 + (a11 - a10) * wcx;
            co[c] = top + (bot - top) * wcy;
        }
        float m = co[0];
#pragma unroll
        for (int c = 1; c < 5; c++) m = fmaxf(m, co[c]);
        float e[5], esum = 0.f;
#pragma unroll
        for (int c = 0; c < 5; c++) { e[c] = __expf(co[c] - m); esum += e[c]; }

        float acc = 0.f;
        if (vx && vy) {
            float w00 = (1.f - fy) * (1.f - fx), w01 = (1.f - fy) * fx;
            float w10 = fy * (1.f - fx),          w11 = fy * fx;
            int i00 = y0  * HW + x0,  i01 = y0  * HW + x1i;
            int i10 = y1i * HW + x0,  i11 = y1i * HW + x1i;
#pragma unroll
            for (int c = 0; c < 5; c++) {
                const float* F = bp[c];
                float v = F[i00] * w00 + F[i01] * w01 + F[i10] * w10 + F[i11] * w11;
                acc += v * e[c];
            }
        }
        float z = acc / esum;
        float rr = __fdividef(1.0f, 1.0f + __expf(-z));
        out[obase + (size_t)py * HW + px] = rr;
    }
}

// ---------------- launch ----------------------------------------------------
extern "C" void kernel_launch(void* const* d_in, const int* in_sizes, int n_in,
                              void* d_out, int out_size) {
    const float *test = nullptr, *attn = nullptr, *bases = nullptr, *sem = nullptr;
    for (int i = 0; i < n_in; i++) {
        long long s = in_sizes[i];
        if      (s == (long long)NBATCH * NA * ROWF)  test  = (const float*)d_in[i];
        else if (s == (long long)NBATCH * NA * ATTNF) attn  = (const float*)d_in[i];
        else if (s == (long long)NBATCH * 4 * HW * HW) bases = (const float*)d_in[i];
        else if (s == (long long)NBATCH * 1 * HW * HW) sem   = (const float*)d_in[i];
    }
    float* out = (float*)d_out;

    k_init<<<4, 1024>>>();
    k_hist<<<dim3(64, NBATCH), 256>>>(test);
    k_thresh<<<NBATCH, HBINS>>>();
    k_compact<<<dim3(64, NBATCH), 256>>>(test);
    k_sort<<<NBATCH, 1024>>>();
    k_nms<<<NBATCH, TOPK>>>(test, out);
    k_masks<<<dim3(10, MAXDET, NBATCH), 320>>>(test, attn, bases, sem, out);
}

// round 3
// speedup vs baseline: 1.0975x; 1.0975x over previous
#include <cuda_runtime.h>
#include <cstdint>

#define NBATCH 4
#define NA 25200
#define NCLS 80
#define ROWF 85
#define ATTNF 980
#define AR 14
#define NB5 5
#define CONF 0.25f
#define IOUT 0.45f
#define MAXDET 100
#define TOPK 1024
#define HB 256
#define MAXC 2048
#define HW 160
#define OUTROW 25606
#define TILE_A 60

// ---------------- scratch (device globals; no allocations allowed) ----------
__device__ unsigned int       g_hist[NBATCH * HB];
__device__ int                g_thrBin[NBATCH];
__device__ int                g_candCnt[NBATCH];
__device__ unsigned long long g_candKey[NBATCH * MAXC];
__device__ unsigned long long g_topKey[NBATCH * TOPK];
__device__ int                g_detAnchor[NBATCH * MAXDET];

// ---------------- init: zero hist/counters every replay ---------------------
__global__ void k_init() {
    int t = threadIdx.x;
    if (t < NBATCH * HB) g_hist[t] = 0u;
    if (t < NBATCH) { g_candCnt[t] = 0; g_thrBin[t] = 0; }
}

// ---------------- pass 1: per-batch histogram of scores > CONF --------------
__global__ void k_hist(const float* __restrict__ test) {
    __shared__ float4 tile4[TILE_A * ROWF / 4];   // 1275 float4 = 5100 floats
    __shared__ unsigned int hh[HB];
    float* tile = (float*)tile4;
    const int b = blockIdx.y;
    const int tid = blockIdx.x;          // 0..419
    if (threadIdx.x < HB) hh[threadIdx.x] = 0u;
    const float4* src = (const float4*)(test + ((size_t)b * NA + (size_t)tid * TILE_A) * ROWF);
#pragma unroll
    for (int i = threadIdx.x; i < TILE_A * ROWF / 4; i += 256) tile4[i] = src[i];
    __syncthreads();
    for (int i = threadIdx.x; i < TILE_A * NCLS; i += 256) {
        int a = i / NCLS, c = i - a * NCLS;
        float v = tile[a * ROWF + 5 + c] * tile[a * ROWF + 4];
        if (v > CONF) {
            int bin = (int)(v * 256.0f); bin = bin > 255 ? 255 : bin;
            atomicAdd(&hh[bin], 1u);
        }
    }
    __syncthreads();
    if (threadIdx.x < HB && hh[threadIdx.x])
        atomicAdd(&g_hist[b * HB + threadIdx.x], hh[threadIdx.x]);
}

// ---------------- find bin whose suffix count first reaches TOPK ------------
__global__ void k_thresh() {
    __shared__ unsigned int s[HB];
    const int b = blockIdx.x;
    const int t = threadIdx.x;
    s[t] = g_hist[b * HB + t];
    __syncthreads();
    for (int off = 1; off < HB; off <<= 1) {
        unsigned v = (t + off < HB) ? s[t + off] : 0u;
        __syncthreads();
        s[t] += v;
        __syncthreads();
    }
    if (s[t] >= TOPK && (t == HB - 1 || s[t + 1] < TOPK)) g_thrBin[b] = t;
}

// ---------------- pass 2: compact candidates (bin >= thr) -------------------
__global__ void k_compact(const float* __restrict__ test) {
    __shared__ float4 tile4[TILE_A * ROWF / 4];
    float* tile = (float*)tile4;
    const int b   = blockIdx.y;
    const int tid = blockIdx.x;
    const int thr = g_thrBin[b];
    const float4* src = (const float4*)(test + ((size_t)b * NA + (size_t)tid * TILE_A) * ROWF);
#pragma unroll
    for (int i = threadIdx.x; i < TILE_A * ROWF / 4; i += 256) tile4[i] = src[i];
    __syncthreads();
    for (int i = threadIdx.x; i < TILE_A * NCLS; i += 256) {
        int a = i / NCLS, c = i - a * NCLS;
        float v = tile[a * ROWF + 5 + c] * tile[a * ROWF + 4];
        if (v > CONF) {
            int bin = (int)(v * 256.0f); bin = bin > 255 ? 255 : bin;
            if (bin >= thr) {
                int pos = atomicAdd(&g_candCnt[b], 1);
                if (pos < MAXC) {
                    unsigned flat = (unsigned)((tid * TILE_A + a) * NCLS + c);
                    g_candKey[b * MAXC + pos] =
                        ((unsigned long long)__float_as_uint(v) << 32) |
                        (unsigned long long)(0xFFFFFFFFu - flat);
                }
            }
        }
    }
}

// ---------------- bitonic sort 2048 keys desc; emit top 1024 ----------------
__global__ void k_sort() {
    __shared__ unsigned long long s[MAXC];
    const int b = blockIdx.x;
    int cnt = g_candCnt[b]; if (cnt > MAXC) cnt = MAXC;
    for (int i = threadIdx.x; i < MAXC; i += blockDim.x)
        s[i] = (i < cnt) ? g_candKey[b * MAXC + i] : 0x00000000FFFFFFFFull;
    __syncthreads();
    for (int k = 2; k <= MAXC; k <<= 1) {
        for (int j = k >> 1; j > 0; j >>= 1) {
            for (int i = threadIdx.x; i < MAXC; i += blockDim.x) {
                int ixj = i ^ j;
                if (ixj > i) {
                    unsigned long long a = s[i], bb = s[ixj];
                    bool up = (i & k) == 0;
                    if (up ? (a < bb) : (a > bb)) { s[i] = bb; s[ixj] = a; }
                }
            }
            __syncthreads();
        }
    }
    for (int i = threadIdx.x; i < TOPK; i += blockDim.x)
        g_topKey[b * TOPK + i] = s[i];
}

// ---------------- greedy class-aware NMS (256 thr x 4 cands) ----------------
__global__ void k_nms(const float* __restrict__ test, float* __restrict__ out) {
    __shared__ float sbx1[TOPK], sby1[TOPK], sbx2[TOPK], sby2[TOPK], sar[TOPK], sval[TOPK];
    __shared__ int   scls[TOPK], sanc[TOPK];
    __shared__ unsigned int vword[TOPK / 32];
    __shared__ int sj;
    const int b = blockIdx.x;
    const int t = threadIdx.x;
    const int lane = t & 31, wid = t >> 5;

#pragma unroll
    for (int s = 0; s < 4; s++) {
        int c = s * 256 + t;
        unsigned long long key = g_topKey[b * TOPK + c];
        float v = __uint_as_float((unsigned)(key >> 32));
        unsigned flat = 0xFFFFFFFFu - (unsigned)(key & 0xFFFFFFFFull);
        bool valid = v > CONF;
        int anc = valid ? (int)(flat / NCLS) : 0;
        int cls = valid ? (int)(flat - (unsigned)anc * NCLS) : 0;
        const float* r = test + ((size_t)b * NA + anc) * ROWF;
        float cx = r[0], cy = r[1], w = r[2], h = r[3];
        float x1 = cx - 0.5f * w, y1 = cy - 0.5f * h;
        float x2 = cx + 0.5f * w, y2 = cy + 0.5f * h;
        sbx1[c] = x1; sby1[c] = y1; sbx2[c] = x2; sby2[c] = y2;
        sar[c] = fmaxf(x2 - x1, 0.f) * fmaxf(y2 - y1, 0.f);
        sval[c] = v; scls[c] = cls; sanc[c] = anc;
        unsigned bal = __ballot_sync(0xFFFFFFFFu, valid);
        if (lane == 0) vword[s * 8 + wid] = bal;
    }
    __syncthreads();

    for (int det = 0; det < MAXDET; det++) {
        if (t < 32) {
            unsigned m   = vword[t];
            unsigned act = __ballot_sync(0xFFFFFFFFu, m != 0);
            int wsel = act ? (__ffs(act) - 1) : 0;
            unsigned mw = __shfl_sync(0xFFFFFFFFu, m, wsel);
            if (t == 0) sj = act ? (wsel * 32 + __ffs(mw) - 1) : -1;
        }
        __syncthreads();
        int j = sj;
        if (t == 0) {
            size_t ob = (size_t)(b * MAXDET + det) * OUTROW;
            if (j >= 0) {
                out[ob + 0] = sbx1[j]; out[ob + 1] = sby1[j];
                out[ob + 2] = sbx2[j]; out[ob + 3] = sby2[j];
                out[ob + 4] = sval[j]; out[ob + 5] = (float)scls[j];
                g_detAnchor[b * MAXDET + det] = sanc[j];
            } else {
                out[ob+0]=0.f; out[ob+1]=0.f; out[ob+2]=0.f;
                out[ob+3]=0.f; out[ob+4]=0.f; out[ob+5]=0.f;
                g_detAnchor[b * MAXDET + det] = 0;
            }
        }
#pragma unroll
        for (int s = 0; s < 4; s++) {
            int c = s * 256 + t;
            bool sup = false;
            if (j >= 0) {
                unsigned vw = vword[s * 8 + wid];
                if ((vw >> lane) & 1u) {
                    if (c == j) sup = true;
                    else if (scls[c] == scls[j]) {
                        float lx = fmaxf(sbx1[c], sbx1[j]), ly = fmaxf(sby1[c], sby1[j]);
                        float rx = fminf(sbx2[c], sbx2[j]), ry = fminf(sby2[c], sby2[j]);
                        float iw = fmaxf(rx - lx, 0.f), ih = fmaxf(ry - ly, 0.f);
                        float inter = iw * ih;
                        float iou = inter / (sar[c] + sar[j] - inter + 1e-9f);
                        sup = iou > IOUT;
                    }
                }
            }
            unsigned sm = __ballot_sync(0xFFFFFFFFu, sup);
            if (lane == 0) vword[s * 8 + wid] &= ~sm;
        }
        __syncthreads();
    }
}

// ---------------- masks: smem ROI patch + separable bilinear ----------------
// box w,h <= 120 px -> ROI spans <= 30 texels; per-block (40 rows) patch <= 10x32.
__global__ void k_masks(const float* __restrict__ test,
                        const float* __restrict__ attn,
                        const float* __restrict__ bases,
                        const float* __restrict__ sem,
                        float* __restrict__ out) {
    __shared__ float sA[NB5 * AR * AR];     // 980
    __shared__ float patch[5 * 10 * 33];    // 1650
    __shared__ float rowv[3 * 5 * 33];      // 495
    __shared__ float tmpc[3 * 5 * AR];      // 210
    const int b   = blockIdx.z;
    const int det = blockIdx.y;
    const int t   = threadIdx.x;            // 0..479
    const int anc = g_detAnchor[b * MAXDET + det];

    // box params (computed redundantly by all threads; broadcast loads)
    const float* r = test + ((size_t)b * NA + anc) * ROWF;
    float cx = __ldg(r), cy = __ldg(r + 1), w = __ldg(r + 2), h = __ldg(r + 3);
    float bx1 = cx - 0.5f * w, by1 = cy - 0.5f * h;
    float bx2 = cx + 0.5f * w, by2 = cy + 0.5f * h;
    float X1 = bx1 * 0.25f - 0.5f, Y1 = by1 * 0.25f - 0.5f;
    float X2 = bx2 * 0.25f - 0.5f, Y2 = by2 * 0.25f - 0.5f;
    float DX = (X2 - X1) / (float)HW;
    float DY = (Y2 - Y1) / (float)HW;

    const int py0 = blockIdx.x * 40;

    // patch bounds (monotonic since w,h >= 0)
    float sxa = X1 + 0.5f * DX,  sxb = X1 + 159.5f * DX;
    int x_lo  = (int)floorf(fminf(fmaxf(sxa, 0.f), 159.f));
    int x_hi2 = min((int)floorf(fminf(fmaxf(sxb, 0.f), 159.f)) + 1, HW - 1);
    int W_p   = x_hi2 - x_lo + 1;                       // <= 32
    float sya = Y1 + (py0 + 0.5f) * DY, syb = Y1 + (py0 + 39.5f) * DY;
    int y_lo  = (int)floorf(fminf(fmaxf(sya, 0.f), 159.f));
    int y_hi2 = min((int)floorf(fminf(fmaxf(syb, 0.f), 159.f)) + 1, HW - 1);
    int H_p   = y_hi2 - y_lo + 1;                       // <= 10

    // load attn coeffs (float4)
    {
        const float4* ap = (const float4*)(attn + ((size_t)b * NA + anc) * ATTNF);
        for (int i = t; i < ATTNF / 4; i += 480) ((float4*)sA)[i] = ap[i];
    }
    // load ROI patch (32 columns fixed, H_p rows, 5 channels)
#pragma unroll
    for (int c = 0; c < 5; c++) {
        const float* F = (c < 4) ? bases + (size_t)(b * 4 + c) * (HW * HW)
                                 : sem + (size_t)b * (HW * HW);
        for (int i = t; i < H_p * 32; i += 480) {
            int yy = i >> 5, xx = i & 31;
            int gx = min(x_lo + xx, HW - 1);
            patch[(c * 10 + yy) * 33 + xx] = __ldg(F + (y_lo + yy) * HW + gx);
        }
    }
    __syncthreads();

    // per-thread x-side precompute (fixed across rows)
    const int lr = t / HW;            // 0..2
    const int px = t - lr * HW;       // 0..159
    float sx = X1 + (px + 0.5f) * DX;
    bool  vx = (sx > -1.0f) && (sx < (float)HW);
    float cxc = fminf(fmaxf(sx, 0.0f), (float)(HW - 1));
    float fxl = floorf(cxc);
    int   x0p = (int)fxl - x_lo;
    int   x1p = min((int)fxl + 1, HW - 1) - x_lo;
    float fx  = cxc - fxl;

    float txc = (px + 0.5f) * ((float)AR / (float)HW) - 0.5f;
    txc = fminf(fmaxf(txc, 0.0f), (float)(AR - 1));
    float ftx = floorf(txc);
    int   cx0 = (int)ftx;
    int   cx1 = min(cx0 + 1, AR - 1);
    float wcx = txc - ftx;

    const size_t obase = (size_t)(b * MAXDET + det) * OUTROW + 6;

    for (int pass = 0; pass < 14; pass++) {
        int local = pass * 3 + lr;
        int py = py0 + local;
        bool rowok = local < 40;

        float fy = 0.f; int y0p = 0, y1p = 0; bool vy = false;
        if (rowok) {
            float sy = Y1 + (py + 0.5f) * DY;
            vy = (sy > -1.0f) && (sy < (float)HW);
            float cyc = fminf(fmaxf(sy, 0.0f), (float)(HW - 1));
            float fyl = floorf(cyc);
            y0p = (int)fyl - y_lo;
            y1p = min((int)fyl + 1, HW - 1) - y_lo;
            fy = cyc - fyl;
        }
        // prep rowv: one item per thread (c = px/32, x = px%32)
        {
            int c = px >> 5, x = px & 31;
            if (rowok && x < W_p) {
                float a0 = patch[(c * 10 + y0p) * 33 + x];
                float a1 = patch[(c * 10 + y1p) * 33 + x];
                rowv[(lr * 5 + c) * 33 + x] = a0 + (a1 - a0) * fy;
            }
        }
        // prep coeff y-blend: 210 items
        if (t < 3 * 5 * AR) {
            int l2 = t / (5 * AR), jj = t - l2 * (5 * AR);
            int c = jj / AR, k = jj - c * AR;
            int loc2 = pass * 3 + l2;
            if (loc2 < 40) {
                int py2 = py0 + loc2;
                float tyc = (py2 + 0.5f) * ((float)AR / (float)HW) - 0.5f;
                tyc = fminf(fmaxf(tyc, 0.0f), (float)(AR - 1));
                float fty = floorf(tyc);
                int cy0 = (int)fty, cy1 = min(cy0 + 1, AR - 1);
                float wy2 = tyc - fty;
                float a0 = sA[c * (AR * AR) + cy0 * AR + k];
                float a1 = sA[c * (AR * AR) + cy1 * AR + k];
                tmpc[(l2 * 5 + c) * AR + k] = a0 + (a1 - a0) * wy2;
            }
        }
        __syncthreads();

        if (rowok) {
            float co[5];
#pragma unroll
            for (int c = 0; c < 5; c++) {
                float t0 = tmpc[(lr * 5 + c) * AR + cx0];
                float t1 = tmpc[(lr * 5 + c) * AR + cx1];
                co[c] = t0 + (t1 - t0) * wcx;
            }
            float m = co[0];
#pragma unroll
            for (int c = 1; c < 5; c++) m = fmaxf(m, co[c]);
            float e[5], esum = 0.f;
#pragma unroll
            for (int c = 0; c < 5; c++) { e[c] = __expf(co[c] - m); esum += e[c]; }

            float acc = 0.f;
            if (vx && vy) {
#pragma unroll
                for (int c = 0; c < 5; c++) {
                    float r0 = rowv[(lr * 5 + c) * 33 + x0p];
                    float r1 = rowv[(lr * 5 + c) * 33 + x1p];
                    acc += (r0 + (r1 - r0) * fx) * e[c];
                }
            }
            float z = acc / esum;
            out[obase + (size_t)py * HW + px] = __fdividef(1.0f, 1.0f + __expf(-z));
        }
        __syncthreads();
    }
}

// ---------------- launch ----------------------------------------------------
extern "C" void kernel_launch(void* const* d_in, const int* in_sizes, int n_in,
                              void* d_out, int out_size) {
    const float *test = nullptr, *attn = nullptr, *bases = nullptr, *sem = nullptr;
    for (int i = 0; i < n_in; i++) {
        long long s = in_sizes[i];
        if      (s == (long long)NBATCH * NA * ROWF)   test  = (const float*)d_in[i];
        else if (s == (long long)NBATCH * NA * ATTNF)  attn  = (const float*)d_in[i];
        else if (s == (long long)NBATCH * 4 * HW * HW) bases = (const float*)d_in[i];
        else if (s == (long long)NBATCH * 1 * HW * HW) sem   = (const float*)d_in[i];
    }
    float* out = (float*)d_out;

    k_init<<<1, 1024>>>();
    k_hist<<<dim3(NA / TILE_A, NBATCH), 256>>>(test);
    k_thresh<<<NBATCH, HB>>>();
    k_compact<<<dim3(NA / TILE_A, NBATCH), 256>>>(test);
    k_sort<<<NBATCH, 1024>>>();
    k_nms<<<NBATCH, 256>>>(test, out);
    k_masks<<<dim3(4, MAXDET, NBATCH), 480>>>(test, attn, bases, sem, out);
}

// round 4
// speedup vs baseline: 1.3797x; 1.2572x over previous
#include <cuda_runtime.h>
#include <cstdint>

#define NBATCH 4
#define NA 25200
#define NCLS 80
#define ROWF 85
#define ATTNF 980
#define AR 14
#define NB5 5
#define CONF 0.25f
#define IOUT 0.45f
#define MAXDET 100
#define TOPK 1024
#define HB 256
#define MAXC 2048
#define HW 160
#define OUTROW 25606
#define TILE_A 60

// ---------------- scratch (device globals; zero-init at load) ---------------
__device__ unsigned int       g_hist[NBATCH * HB];
__device__ int                g_candCnt[NBATCH];
__device__ unsigned long long g_candKey[NBATCH * MAXC];
__device__ int                g_detAnchor[NBATCH * MAXDET];

// ---------------- pass 1: per-batch histogram of scores > CONF --------------
__global__ void k_hist(const float* __restrict__ test) {
    __shared__ float4 tile4[TILE_A * ROWF / 4];
    __shared__ unsigned int hh[HB];
    float* tile = (float*)tile4;
    const int b = blockIdx.y;
    const int tid = blockIdx.x;
    if (threadIdx.x < HB) hh[threadIdx.x] = 0u;
    const float4* src = (const float4*)(test + ((size_t)b * NA + (size_t)tid * TILE_A) * ROWF);
#pragma unroll
    for (int i = threadIdx.x; i < TILE_A * ROWF / 4; i += 256) tile4[i] = src[i];
    __syncthreads();
    for (int i = threadIdx.x; i < TILE_A * NCLS; i += 256) {
        int a = i / NCLS, c = i - a * NCLS;
        float v = tile[a * ROWF + 5 + c] * tile[a * ROWF + 4];
        if (v > CONF) {
            int bin = (int)(v * 256.0f); bin = bin > 255 ? 255 : bin;
            atomicAdd(&hh[bin], 1u);
        }
    }
    __syncthreads();
    if (threadIdx.x < HB && hh[threadIdx.x])
        atomicAdd(&g_hist[b * HB + threadIdx.x], hh[threadIdx.x]);
}

// ---------------- pass 2: compact candidates (thr computed inline) ----------
__global__ void k_compact(const float* __restrict__ test) {
    __shared__ float4 tile4[TILE_A * ROWF / 4];
    __shared__ int s_thr;
    float* tile = (float*)tile4;
    const int b   = blockIdx.y;
    const int tid = blockIdx.x;
    const int t   = threadIdx.x;

    // warp 0: compute threshold bin from global histogram (suffix >= TOPK)
    if (t < 32) {
        int lane = t;
        unsigned h[8];
#pragma unroll
        for (int k = 0; k < 8; k++) h[k] = g_hist[b * HB + lane * 8 + k];
        unsigned tot = 0;
#pragma unroll
        for (int k = 0; k < 8; k++) tot += h[k];
        // run = sum over lanes >= lane
        unsigned run = tot;
#pragma unroll
        for (int off = 1; off < 32; off <<= 1) {
            unsigned v = __shfl_down_sync(0xFFFFFFFFu, run, off);
            if (lane + off < 32) run += v;
        }
        unsigned above = run - tot;   // sum over lanes > lane
        int cand = -1;
        unsigned cum = above;
        for (int k = 7; k >= 0; k--) {
            cum += h[k];
            if (cum >= TOPK) { cand = lane * 8 + k; break; }
        }
        // warp max-reduce
#pragma unroll
        for (int off = 16; off > 0; off >>= 1)
            cand = max(cand, __shfl_xor_sync(0xFFFFFFFFu, cand, off));
        if (lane == 0) s_thr = cand < 0 ? 0 : cand;
    }

    const float4* src = (const float4*)(test + ((size_t)b * NA + (size_t)tid * TILE_A) * ROWF);
#pragma unroll
    for (int i = t; i < TILE_A * ROWF / 4; i += 256) tile4[i] = src[i];
    __syncthreads();
    const int thr = s_thr;
    for (int i = t; i < TILE_A * NCLS; i += 256) {
        int a = i / NCLS, c = i - a * NCLS;
        float v = tile[a * ROWF + 5 + c] * tile[a * ROWF + 4];
        if (v > CONF) {
            int bin = (int)(v * 256.0f); bin = bin > 255 ? 255 : bin;
            if (bin >= thr) {
                int pos = atomicAdd(&g_candCnt[b], 1);
                if (pos < MAXC) {
                    unsigned flat = (unsigned)((tid * TILE_A + a) * NCLS + c);
                    g_candKey[b * MAXC + pos] =
                        ((unsigned long long)__float_as_uint(v) << 32) |
                        (unsigned long long)(0xFFFFFFFFu - flat);
                }
            }
        }
    }
}

// ---------------- sort (bitonic 2048) + greedy NMS, fused -------------------
union SortU {
    unsigned long long s[MAXC];
    struct { int cls[TOPK]; int anc[TOPK]; } post;
};

__global__ void __launch_bounds__(1024, 1) k_sortnms(const float* __restrict__ test,
                                                     float* __restrict__ out) {
    __shared__ SortU u;
    __shared__ float sbx1[TOPK], sby1[TOPK], sbx2[TOPK], sby2[TOPK], sar[TOPK], sval[TOPK];
    __shared__ unsigned int vword[TOPK / 32];
    const int b = blockIdx.x;
    const int t = threadIdx.x;
    const int lane = t & 31, wid = t >> 5;

    int cnt = g_candCnt[b]; if (cnt > MAXC) cnt = MAXC;
    for (int i = t; i < MAXC; i += 1024)
        u.s[i] = (i < cnt) ? g_candKey[b * MAXC + i] : 0x00000000FFFFFFFFull;
    __syncthreads();
    for (int k = 2; k <= MAXC; k <<= 1) {
        for (int j = k >> 1; j > 0; j >>= 1) {
            for (int i = t; i < MAXC; i += 1024) {
                int ixj = i ^ j;
                if (ixj > i) {
                    unsigned long long a = u.s[i], bb = u.s[ixj];
                    bool up = (i & k) == 0;
                    if (up ? (a < bb) : (a > bb)) { u.s[i] = bb; u.s[ixj] = a; }
                }
            }
            __syncthreads();
        }
    }
    // extract own candidate (top-1024) into regs, then repurpose union memory
    unsigned long long key = u.s[t];
    __syncthreads();

    float v = __uint_as_float((unsigned)(key >> 32));
    unsigned flat = 0xFFFFFFFFu - (unsigned)(key & 0xFFFFFFFFull);
    bool valid = v > CONF;
    int anc = valid ? (int)(flat / NCLS) : 0;
    int cls = valid ? (int)(flat - (unsigned)anc * NCLS) : 0;

    const float* r = test + ((size_t)b * NA + anc) * ROWF;
    float cx = r[0], cy = r[1], w = r[2], h = r[3];
    float x1 = cx - 0.5f * w, y1 = cy - 0.5f * h;
    float x2 = cx + 0.5f * w, y2 = cy + 0.5f * h;
    sbx1[t] = x1; sby1[t] = y1; sbx2[t] = x2; sby2[t] = y2;
    sar[t] = fmaxf(x2 - x1, 0.f) * fmaxf(y2 - y1, 0.f);
    sval[t] = v; u.post.cls[t] = cls; u.post.anc[t] = anc;

    unsigned bal = __ballot_sync(0xFFFFFFFFu, valid);
    if (lane == 0) vword[wid] = bal;

    // zero scratch for next replay (safe: this block owns batch b)
    if (t < HB) g_hist[b * HB + t] = 0u;
    if (t == 0) g_candCnt[b] = 0;
    __syncthreads();

    for (int det = 0; det < MAXDET; det++) {
        // every warp computes find-first redundantly (no extra barrier)
        unsigned m   = vword[lane];
        unsigned act = __ballot_sync(0xFFFFFFFFu, m != 0);
        int wsel = act ? (__ffs(act) - 1) : 0;
        unsigned mw = __shfl_sync(0xFFFFFFFFu, m, wsel);
        int j = act ? (wsel * 32 + __ffs(mw) - 1) : -1;

        if (t == 0) {
            size_t ob = (size_t)(b * MAXDET + det) * OUTROW;
            if (j >= 0) {
                out[ob + 0] = sbx1[j]; out[ob + 1] = sby1[j];
                out[ob + 2] = sbx2[j]; out[ob + 3] = sby2[j];
                out[ob + 4] = sval[j]; out[ob + 5] = (float)u.post.cls[j];
                g_detAnchor[b * MAXDET + det] = u.post.anc[j];
            } else {
                out[ob+0]=0.f; out[ob+1]=0.f; out[ob+2]=0.f;
                out[ob+3]=0.f; out[ob+4]=0.f; out[ob+5]=0.f;
                g_detAnchor[b * MAXDET + det] = 0;
            }
        }
        bool sup = false;
        if (j >= 0 && ((vword[wid] >> lane) & 1u)) {
            if (t == j) sup = true;
            else if (cls == u.post.cls[j]) {
                float lx = fmaxf(x1, sbx1[j]), ly = fmaxf(y1, sby1[j]);
                float rx = fminf(x2, sbx2[j]), ry = fminf(y2, sby2[j]);
                float iw = fmaxf(rx - lx, 0.f), ih = fmaxf(ry - ly, 0.f);
                float inter = iw * ih;
                float iou = inter / (sar[t] + sar[j] - inter + 1e-9f);
                sup = iou > IOUT;
            }
        }
        unsigned sm = __ballot_sync(0xFFFFFFFFu, sup);
        if (lane == 0) vword[wid] &= ~sm;
        __syncthreads();
    }
}

// ---------------- masks: 1 det/block, warp-autonomous rows ------------------
__global__ void __launch_bounds__(512) k_masks(const float* __restrict__ test,
                        const float* __restrict__ attn,
                        const float* __restrict__ bases,
                        const float* __restrict__ sem,
                        float* __restrict__ out) {
    __shared__ float sA[NB5 * AR * AR];        // 980
    __shared__ float patch[5 * 32 * 33];       // 5280
    __shared__ float tmpc[16 * 72];            // per-warp coeff rows
    const int b   = blockIdx.y;
    const int det = blockIdx.x;
    const int t   = threadIdx.x;               // 0..511
    const int lane = t & 31, wid = t >> 5;
    const int anc = g_detAnchor[b * MAXDET + det];

    const float* r = test + ((size_t)b * NA + anc) * ROWF;
    float cx = __ldg(r), cy = __ldg(r + 1), w = __ldg(r + 2), h = __ldg(r + 3);
    float bx1 = cx - 0.5f * w, by1 = cy - 0.5f * h;
    float bx2 = cx + 0.5f * w, by2 = cy + 0.5f * h;
    float X1 = bx1 * 0.25f - 0.5f, Y1 = by1 * 0.25f - 0.5f;
    float X2 = bx2 * 0.25f - 0.5f, Y2 = by2 * 0.25f - 0.5f;
    float DX = (X2 - X1) / (float)HW;
    float DY = (Y2 - Y1) / (float)HW;

    // patch bounds (ROI texel span <= 32 in each axis)
    float sxa = X1 + 0.5f * DX,  sxb = X1 + 159.5f * DX;
    int x_lo  = (int)floorf(fminf(fmaxf(sxa, 0.f), 159.f));
    float sya = Y1 + 0.5f * DY,  syb = Y1 + 159.5f * DY;
    int y_lo  = (int)floorf(fminf(fmaxf(sya, 0.f), 159.f));

    // load attn coeffs (float4)
    {
        const float4* ap = (const float4*)(attn + ((size_t)b * NA + anc) * ATTNF);
        for (int i = t; i < ATTNF / 4; i += 512) ((float4*)sA)[i] = ap[i];
    }
    // load ROI patch: 5 channels x 32 rows x 32 cols (clamped)
#pragma unroll
    for (int c = 0; c < 5; c++) {
        const float* F = (c < 4) ? bases + (size_t)(b * 4 + c) * (HW * HW)
                                 : sem + (size_t)b * (HW * HW);
        for (int i = t; i < 32 * 32; i += 512) {
            int yy = i >> 5, xx = i & 31;
            int gy = min(y_lo + yy, HW - 1);
            int gx = min(x_lo + xx, HW - 1);
            patch[(c * 32 + yy) * 33 + xx] = __ldg(F + gy * HW + gx);
        }
    }
    __syncthreads();

    float* tw = tmpc + wid * 72;
    const size_t obase = (size_t)(b * MAXDET + det) * OUTROW + 6;

    for (int py = wid; py < HW; py += 16) {
        // y-side roi params
        float sy = Y1 + (py + 0.5f) * DY;
        bool  vy = (sy > -1.0f) && (sy < (float)HW);
        float cyc = fminf(fmaxf(sy, 0.0f), (float)(HW - 1));
        float fyl = floorf(cyc);
        int   y0p = (int)fyl - y_lo;
        int   y1p = min((int)fyl + 1, HW - 1) - y_lo;
        float fy  = cyc - fyl;

        // y-blend ROI row into registers (lane = patch column)
        float rv[5];
#pragma unroll
        for (int c = 0; c < 5; c++) {
            float a0 = patch[(c * 32 + y0p) * 33 + lane];
            float a1 = patch[(c * 32 + y1p) * 33 + lane];
            rv[c] = a0 + (a1 - a0) * fy;
        }

        // y-blend coeff row (70 values) into per-warp smem
        float tyc = (py + 0.5f) * ((float)AR / (float)HW) - 0.5f;
        tyc = fminf(fmaxf(tyc, 0.0f), (float)(AR - 1));
        float fty = floorf(tyc);
        int cy0 = (int)fty, cy1 = min(cy0 + 1, AR - 1);
        float wy2 = tyc - fty;
        for (int i = lane; i < 5 * AR; i += 32) {
            int c = i / AR, k = i - c * AR;
            float a0 = sA[c * (AR * AR) + cy0 * AR + k];
            float a1 = sA[c * (AR * AR) + cy1 * AR + k];
            tw[i] = a0 + (a1 - a0) * wy2;
        }
        __syncwarp();

#pragma unroll
        for (int sub = 0; sub < 5; sub++) {
            int px = sub * 32 + lane;
            // x-side roi params
            float sx = X1 + (px + 0.5f) * DX;
            bool  vx = (sx > -1.0f) && (sx < (float)HW);
            float cxc = fminf(fmaxf(sx, 0.0f), (float)(HW - 1));
            float fxl = floorf(cxc);
            int   x0p = (int)fxl - x_lo;
            int   x1p = min((int)fxl + 1, HW - 1) - x_lo;
            float fx  = cxc - fxl;
            // x-side coeff params
            float txc = (px + 0.5f) * ((float)AR / (float)HW) - 0.5f;
            txc = fminf(fmaxf(txc, 0.0f), (float)(AR - 1));
            float ftx = floorf(txc);
            int   cx0 = (int)ftx;
            int   cx1 = min(cx0 + 1, AR - 1);
            float wcx = txc - ftx;

            float co[5];
#pragma unroll
            for (int c = 0; c < 5; c++) {
                float t0 = tw[c * AR + cx0];
                float t1 = tw[c * AR + cx1];
                co[c] = t0 + (t1 - t0) * wcx;
            }
            float m = co[0];
#pragma unroll
            for (int c = 1; c < 5; c++) m = fmaxf(m, co[c]);
            float e[5], esum = 0.f;
#pragma unroll
            for (int c = 0; c < 5; c++) { e[c] = __expf(co[c] - m); esum += e[c]; }

            float acc = 0.f;
            if (vx && vy) {
#pragma unroll
                for (int c = 0; c < 5; c++) {
                    float r0 = __shfl_sync(0xFFFFFFFFu, rv[c], x0p);
                    float r1 = __shfl_sync(0xFFFFFFFFu, rv[c], x1p);
                    acc += (r0 + (r1 - r0) * fx) * e[c];
                }
            } else {
#pragma unroll
                for (int c = 0; c < 5; c++) {
                    __shfl_sync(0xFFFFFFFFu, rv[c], x0p);
                    __shfl_sync(0xFFFFFFFFu, rv[c], x1p);
                }
            }
            float z = acc / esum;
            out[obase + (size_t)py * HW + px] = __fdividef(1.0f, 1.0f + __expf(-z));
        }
        __syncwarp();
    }
}

// ---------------- launch ----------------------------------------------------
extern "C" void kernel_launch(void* const* d_in, const int* in_sizes, int n_in,
                              void* d_out, int out_size) {
    const float *test = nullptr, *attn = nullptr, *bases = nullptr, *sem = nullptr;
    for (int i = 0; i < n_in; i++) {
        long long s = in_sizes[i];
        if      (s == (long long)NBATCH * NA * ROWF)   test  = (const float*)d_in[i];
        else if (s == (long long)NBATCH * NA * ATTNF)  attn  = (const float*)d_in[i];
        else if (s == (long long)NBATCH * 4 * HW * HW) bases = (const float*)d_in[i];
        else if (s == (long long)NBATCH * 1 * HW * HW) sem   = (const float*)d_in[i];
    }
    float* out = (float*)d_out;

    k_hist<<<dim3(NA / TILE_A, NBATCH), 256>>>(test);
    k_compact<<<dim3(NA / TILE_A, NBATCH), 256>>>(test);
    k_sortnms<<<NBATCH, 1024>>>(test, out);
    k_masks<<<dim3(MAXDET, NBATCH), 512>>>(test, attn, bases, sem, out);
}

// round 5
// speedup vs baseline: 1.5723x; 1.1396x over previous
#include <cuda_runtime.h>
#include <cstdint>

#define NBATCH 4
#define NA 25200
#define NCLS 80
#define ROWF 85
#define ATTNF 980
#define AR 14
#define NB5 5
#define CONF 0.25f
#define IOUT 0.45f
#define MAXDET 100
#define TOPK 1024
#define HB 256
#define MAXC 2048
#define HW 160
#define OUTROW 25606
#define TILE_A 60

// ---------------- scratch (device globals; zero-init at load) ---------------
__device__ unsigned int       g_hist[NBATCH * HB];
__device__ int                g_candCnt[NBATCH];
__device__ unsigned long long g_candKey[NBATCH * MAXC];
__device__ int                g_detAnchor[NBATCH * MAXDET];

// ---------------- pass 1: per-batch histogram of scores > CONF --------------
__global__ void k_hist(const float* __restrict__ test) {
    __shared__ float4 tile4[TILE_A * ROWF / 4];
    __shared__ unsigned int hh[HB];
    float* tile = (float*)tile4;
    const int b = blockIdx.y;
    const int tid = blockIdx.x;
    if (threadIdx.x < HB) hh[threadIdx.x] = 0u;
    const float4* src = (const float4*)(test + ((size_t)b * NA + (size_t)tid * TILE_A) * ROWF);
#pragma unroll
    for (int i = threadIdx.x; i < TILE_A * ROWF / 4; i += 256) tile4[i] = src[i];
    __syncthreads();
    for (int i = threadIdx.x; i < TILE_A * NCLS; i += 256) {
        int a = i / NCLS, c = i - a * NCLS;
        float v = tile[a * ROWF + 5 + c] * tile[a * ROWF + 4];
        if (v > CONF) {
            int bin = (int)(v * 256.0f); bin = bin > 255 ? 255 : bin;
            atomicAdd(&hh[bin], 1u);
        }
    }
    __syncthreads();
    if (threadIdx.x < HB && hh[threadIdx.x])
        atomicAdd(&g_hist[b * HB + threadIdx.x], hh[threadIdx.x]);
}

// ---------------- pass 2: compact candidates (thr computed inline) ----------
__global__ void k_compact(const float* __restrict__ test) {
    __shared__ float4 tile4[TILE_A * ROWF / 4];
    __shared__ int s_thr;
    float* tile = (float*)tile4;
    const int b   = blockIdx.y;
    const int tid = blockIdx.x;
    const int t   = threadIdx.x;

    if (t < 32) {
        int lane = t;
        unsigned h[8];
#pragma unroll
        for (int k = 0; k < 8; k++) h[k] = g_hist[b * HB + lane * 8 + k];
        unsigned tot = 0;
#pragma unroll
        for (int k = 0; k < 8; k++) tot += h[k];
        unsigned run = tot;
#pragma unroll
        for (int off = 1; off < 32; off <<= 1) {
            unsigned v = __shfl_down_sync(0xFFFFFFFFu, run, off);
            if (lane + off < 32) run += v;
        }
        unsigned above = run - tot;
        int cand = -1;
        unsigned cum = above;
        for (int k = 7; k >= 0; k--) {
            cum += h[k];
            if (cum >= TOPK) { cand = lane * 8 + k; break; }
        }
#pragma unroll
        for (int off = 16; off > 0; off >>= 1)
            cand = max(cand, __shfl_xor_sync(0xFFFFFFFFu, cand, off));
        if (lane == 0) s_thr = cand < 0 ? 0 : cand;
    }

    const float4* src = (const float4*)(test + ((size_t)b * NA + (size_t)tid * TILE_A) * ROWF);
#pragma unroll
    for (int i = t; i < TILE_A * ROWF / 4; i += 256) tile4[i] = src[i];
    __syncthreads();
    const int thr = s_thr;
    for (int i = t; i < TILE_A * NCLS; i += 256) {
        int a = i / NCLS, c = i - a * NCLS;
        float v = tile[a * ROWF + 5 + c] * tile[a * ROWF + 4];
        if (v > CONF) {
            int bin = (int)(v * 256.0f); bin = bin > 255 ? 255 : bin;
            if (bin >= thr) {
                int pos = atomicAdd(&g_candCnt[b], 1);
                if (pos < MAXC) {
                    unsigned flat = (unsigned)((tid * TILE_A + a) * NCLS + c);
                    g_candKey[b * MAXC + pos] =
                        ((unsigned long long)__float_as_uint(v) << 32) |
                        (unsigned long long)(0xFFFFFFFFu - flat);
                }
            }
        }
    }
}

// ---------------- hybrid bitonic helpers ------------------------------------
__device__ __forceinline__ unsigned long long cex_shfl(unsigned long long v, int i, int j, int k) {
    unsigned long long pv = __shfl_xor_sync(0xFFFFFFFFu, v, j);
    bool lower = ((i & j) == 0);
    bool desc  = ((i & k) == 0);
    return (desc == lower) ? (v > pv ? v : pv) : (v < pv ? v : pv);
}
__device__ __forceinline__ void cex_reg(unsigned long long& v0, unsigned long long& v1, int i0, int k) {
    bool desc = ((i0 & k) == 0);
    unsigned long long a = v0, b = v1;
    if (desc ? (a < b) : (a > b)) { v0 = b; v1 = a; }
}

// ---------------- sort (hybrid bitonic 2048) + greedy NMS, fused ------------
union SortU {
    unsigned long long s[MAXC];
    struct { int cls[TOPK]; int anc[TOPK]; } post;
};

__global__ void __launch_bounds__(1024, 1) k_sortnms(const float* __restrict__ test,
                                                     float* __restrict__ out) {
    __shared__ SortU u;
    __shared__ float sbx1[TOPK], sby1[TOPK], sbx2[TOPK], sby2[TOPK], sar[TOPK], sval[TOPK];
    __shared__ unsigned int vword[TOPK / 32];
    const int b = blockIdx.x;
    const int t = threadIdx.x;
    const int lane = t & 31, wid = t >> 5;
    const int base = wid * 64;
    const int i0 = base + lane, i1 = base + 32 + lane;

    int cnt = g_candCnt[b]; if (cnt > MAXC) cnt = MAXC;

    // load this warp's 64 elements directly into registers
    unsigned long long v0 = (i0 < cnt) ? g_candKey[b * MAXC + i0] : 0x00000000FFFFFFFFull;
    unsigned long long v1 = (i1 < cnt) ? g_candKey[b * MAXC + i1] : 0x00000000FFFFFFFFull;

    // Phase A: k = 2..64 entirely warp-local
#pragma unroll
    for (int k = 2; k <= 64; k <<= 1) {
#pragma unroll
        for (int j = k >> 1; j >= 1; j >>= 1) {
            if (j == 32) cex_reg(v0, v1, i0, k);
            else { v0 = cex_shfl(v0, i0, j, k); v1 = cex_shfl(v1, i1, j, k); }
        }
    }
    u.s[i0] = v0; u.s[i1] = v1;
    __syncthreads();

    // Phase B: k = 128..2048; smem rounds for j>=64, warp-local tail j<=32
    for (int k = 128; k <= MAXC; k <<= 1) {
        for (int j = k >> 1; j >= 64; j >>= 1) {
#pragma unroll
            for (int i = t; i < MAXC; i += 1024) {
                int ixj = i ^ j;
                if (ixj > i) {
                    unsigned long long a = u.s[i], bb = u.s[ixj];
                    bool up = (i & k) == 0;
                    if (up ? (a < bb) : (a > bb)) { u.s[i] = bb; u.s[ixj] = a; }
                }
            }
            __syncthreads();
        }
        v0 = u.s[i0]; v1 = u.s[i1];
        cex_reg(v0, v1, i0, k);
#pragma unroll
        for (int j = 16; j >= 1; j >>= 1) {
            v0 = cex_shfl(v0, i0, j, k);
            v1 = cex_shfl(v1, i1, j, k);
        }
        u.s[i0] = v0; u.s[i1] = v1;
        __syncthreads();
    }

    unsigned long long key = u.s[t];
    __syncthreads();

    float v = __uint_as_float((unsigned)(key >> 32));
    unsigned flat = 0xFFFFFFFFu - (unsigned)(key & 0xFFFFFFFFull);
    bool valid = v > CONF;
    int anc = valid ? (int)(flat / NCLS) : 0;
    int cls = valid ? (int)(flat - (unsigned)anc * NCLS) : 0;

    const float* r = test + ((size_t)b * NA + anc) * ROWF;
    float cx = r[0], cy = r[1], w = r[2], h = r[3];
    float x1 = cx - 0.5f * w, y1 = cy - 0.5f * h;
    float x2 = cx + 0.5f * w, y2 = cy + 0.5f * h;
    sbx1[t] = x1; sby1[t] = y1; sbx2[t] = x2; sby2[t] = y2;
    sar[t] = fmaxf(x2 - x1, 0.f) * fmaxf(y2 - y1, 0.f);
    sval[t] = v; u.post.cls[t] = cls; u.post.anc[t] = anc;

    unsigned bal = __ballot_sync(0xFFFFFFFFu, valid);
    if (lane == 0) vword[wid] = bal;

    // zero scratch for next replay
    if (t < HB) g_hist[b * HB + t] = 0u;
    if (t == 0) g_candCnt[b] = 0;
    __syncthreads();

    for (int det = 0; det < MAXDET; det++) {
        unsigned m   = vword[lane];
        unsigned act = __ballot_sync(0xFFFFFFFFu, m != 0);
        int wsel = act ? (__ffs(act) - 1) : 0;
        unsigned mw = __shfl_sync(0xFFFFFFFFu, m, wsel);
        int j = act ? (wsel * 32 + __ffs(mw) - 1) : -1;

        if (t == 0) {
            size_t ob = (size_t)(b * MAXDET + det) * OUTROW;
            if (j >= 0) {
                out[ob + 0] = sbx1[j]; out[ob + 1] = sby1[j];
                out[ob + 2] = sbx2[j]; out[ob + 3] = sby2[j];
                out[ob + 4] = sval[j]; out[ob + 5] = (float)u.post.cls[j];
                g_detAnchor[b * MAXDET + det] = u.post.anc[j];
            } else {
                out[ob+0]=0.f; out[ob+1]=0.f; out[ob+2]=0.f;
                out[ob+3]=0.f; out[ob+4]=0.f; out[ob+5]=0.f;
                g_detAnchor[b * MAXDET + det] = 0;
            }
        }
        bool sup = false;
        if (j >= 0 && ((vword[wid] >> lane) & 1u)) {
            if (t == j) sup = true;
            else if (cls == u.post.cls[j]) {
                float lx = fmaxf(x1, sbx1[j]), ly = fmaxf(y1, sby1[j]);
                float rx = fminf(x2, sbx2[j]), ry = fminf(y2, sby2[j]);
                float iw = fmaxf(rx - lx, 0.f), ih = fmaxf(ry - ly, 0.f);
                float inter = iw * ih;
                float iou = inter / (sar[t] + sar[j] - inter + 1e-9f);
                sup = iou > IOUT;
            }
        }
        unsigned sm = __ballot_sync(0xFFFFFFFFu, sup);
        if (lane == 0) vword[wid] &= ~sm;
        __syncthreads();
    }
}

// ---------------- masks: 1 det/block, warp-autonomous, x-param tables -------
__global__ void __launch_bounds__(512) k_masks(const float* __restrict__ test,
                        const float* __restrict__ attn,
                        const float* __restrict__ bases,
                        const float* __restrict__ sem,
                        float* __restrict__ out) {
    __shared__ float sA[NB5 * AR * AR];        // 980
    __shared__ float patch[5 * 32 * 33];       // 5280
    __shared__ float tmpc[16 * 72];            // per-warp y-blended coeff rows
    __shared__ float sfx[HW], swcx[HW];
    __shared__ int   spack[HW];
    const int b   = blockIdx.y;
    const int det = blockIdx.x;
    const int t   = threadIdx.x;
    const int lane = t & 31, wid = t >> 5;
    const int anc = g_detAnchor[b * MAXDET + det];

    const float* r = test + ((size_t)b * NA + anc) * ROWF;
    float cx = __ldg(r), cy = __ldg(r + 1), w = __ldg(r + 2), h = __ldg(r + 3);
    float bx1 = cx - 0.5f * w, by1 = cy - 0.5f * h;
    float bx2 = cx + 0.5f * w, by2 = cy + 0.5f * h;
    float X1 = bx1 * 0.25f - 0.5f, Y1 = by1 * 0.25f - 0.5f;
    float X2 = bx2 * 0.25f - 0.5f, Y2 = by2 * 0.25f - 0.5f;
    float DX = (X2 - X1) / (float)HW;
    float DY = (Y2 - Y1) / (float)HW;

    float sxa = X1 + 0.5f * DX,  sxb = X1 + 159.5f * DX;
    int x_lo  = (int)floorf(fminf(fmaxf(sxa, 0.f), 159.f));
    float sya = Y1 + 0.5f * DY,  syb = Y1 + 159.5f * DY;
    int y_lo  = (int)floorf(fminf(fmaxf(sya, 0.f), 159.f));

    // x-side tables (valid pixels unaffected by the clamps: ROI span < 31 texels)
    if (t < HW) {
        int px = t;
        float sx = X1 + (px + 0.5f) * DX;
        bool  vx = (sx > -1.0f) && (sx < (float)HW);
        float cxc = fminf(fmaxf(sx, 0.0f), (float)(HW - 1));
        float fxl = floorf(cxc);
        int x0p = min(max((int)fxl - x_lo, 0), 31);
        int x1p = min(max(min((int)fxl + 1, HW - 1) - x_lo, 0), 31);
        sfx[px] = cxc - fxl;

        float txc = (px + 0.5f) * ((float)AR / (float)HW) - 0.5f;
        txc = fminf(fmaxf(txc, 0.0f), (float)(AR - 1));
        float ftx = floorf(txc);
        int cx0 = (int)ftx;
        int cx1 = min(cx0 + 1, AR - 1);
        swcx[px] = txc - ftx;
        spack[px] = x0p | (x1p << 6) | (cx0 << 12) | (cx1 << 17) | (vx ? (1 << 22) : 0);
    }
    {
        const float4* ap = (const float4*)(attn + ((size_t)b * NA + anc) * ATTNF);
        for (int i = t; i < ATTNF / 4; i += 512) ((float4*)sA)[i] = ap[i];
    }
#pragma unroll
    for (int c = 0; c < 5; c++) {
        const float* F = (c < 4) ? bases + (size_t)(b * 4 + c) * (HW * HW)
                                 : sem + (size_t)b * (HW * HW);
        for (int i = t; i < 32 * 32; i += 512) {
            int yy = i >> 5, xx = i & 31;
            int gy = min(y_lo + yy, HW - 1);
            int gx = min(x_lo + xx, HW - 1);
            patch[(c * 32 + yy) * 33 + xx] = __ldg(F + gy * HW + gx);
        }
    }
    __syncthreads();

    float* tw = tmpc + wid * 72;
    const size_t obase = (size_t)(b * MAXDET + det) * OUTROW + 6;

    for (int py = wid; py < HW; py += 16) {
        float sy = Y1 + (py + 0.5f) * DY;
        bool  vy = (sy > -1.0f) && (sy < (float)HW);
        float cyc = fminf(fmaxf(sy, 0.0f), (float)(HW - 1));
        float fyl = floorf(cyc);
        int   y0p = min(max((int)fyl - y_lo, 0), 31);
        int   y1p = min(max(min((int)fyl + 1, HW - 1) - y_lo, 0), 31);
        float fy  = cyc - fyl;

        float rv[5];
#pragma unroll
        for (int c = 0; c < 5; c++) {
            float a0 = patch[(c * 32 + y0p) * 33 + lane];
            float a1 = patch[(c * 32 + y1p) * 33 + lane];
            rv[c] = a0 + (a1 - a0) * fy;
        }

        float tyc = (py + 0.5f) * ((float)AR / (float)HW) - 0.5f;
        tyc = fminf(fmaxf(tyc, 0.0f), (float)(AR - 1));
        float fty = floorf(tyc);
        int cy0 = (int)fty, cy1 = min(cy0 + 1, AR - 1);
        float wy2 = tyc - fty;
        for (int i = lane; i < 5 * AR; i += 32) {
            int c = i / AR, k = i - c * AR;
            float a0 = sA[c * (AR * AR) + cy0 * AR + k];
            float a1 = sA[c * (AR * AR) + cy1 * AR + k];
            tw[i] = a0 + (a1 - a0) * wy2;
        }
        __syncwarp();

#pragma unroll
        for (int sub = 0; sub < 5; sub++) {
            int px = sub * 32 + lane;
            float fx  = sfx[px];
            float wcx = swcx[px];
            int   pk  = spack[px];
            int x0p = pk & 63, x1p = (pk >> 6) & 63;
            int cx0 = (pk >> 12) & 31, cx1 = (pk >> 17) & 31;
            bool vx = (pk >> 22) & 1;

            float esum = 0.f, acc = 0.f;
#pragma unroll
            for (int c = 0; c < 5; c++) {
                float t0 = tw[c * AR + cx0];
                float t1 = tw[c * AR + cx1];
                float e  = __expf(t0 + (t1 - t0) * wcx);
                esum += e;
                float r0 = __shfl_sync(0xFFFFFFFFu, rv[c], x0p);
                float r1 = __shfl_sync(0xFFFFFFFFu, rv[c], x1p);
                acc += (r0 + (r1 - r0) * fx) * e;
            }
            acc = (vx && vy) ? acc : 0.f;
            float z = acc / esum;
            out[obase + (size_t)py * HW + px] = __fdividef(1.0f, 1.0f + __expf(-z));
        }
        __syncwarp();
    }
}

// ---------------- launch ----------------------------------------------------
extern "C" void kernel_launch(void* const* d_in, const int* in_sizes, int n_in,
                              void* d_out, int out_size) {
    const float *test = nullptr, *attn = nullptr, *bases = nullptr, *sem = nullptr;
    for (int i = 0; i < n_in; i++) {
        long long s = in_sizes[i];
        if      (s == (long long)NBATCH * NA * ROWF)   test  = (const float*)d_in[i];
        else if (s == (long long)NBATCH * NA * ATTNF)  attn  = (const float*)d_in[i];
        else if (s == (long long)NBATCH * 4 * HW * HW) bases = (const float*)d_in[i];
        else if (s == (long long)NBATCH * 1 * HW * HW) sem   = (const float*)d_in[i];
    }
    float* out = (float*)d_out;

    k_hist<<<dim3(NA / TILE_A, NBATCH), 256>>>(test);
    k_compact<<<dim3(NA / TILE_A, NBATCH), 256>>>(test);
    k_sortnms<<<NBATCH, 1024>>>(test, out);
    k_masks<<<dim3(MAXDET, NBATCH), 512>>>(test, attn, bases, sem, out);
}

// round 7
// speedup vs baseline: 1.6338x; 1.0391x over previous
#include <cuda_runtime.h>
#include <cstdint>

#define NBATCH 4
#define NA 25200
#define NCLS 80
#define ROWF 85
#define ATTNF 980
#define AR 14
#define NB5 5
#define CONF 0.25f
#define IOUT 0.45f
#define MAXDET 100
#define TOPK 1024
#define HB 256
#define MAXC 2048
#define HW 160
#define OUTROW 25606
#define TILE_A 60

// ---------------- scratch (device globals; zero-init at load) ---------------
__device__ unsigned int       g_hist[NBATCH * HB];
__device__ int                g_candCnt[NBATCH];
__device__ unsigned long long g_candKey[NBATCH * MAXC];
__device__ int                g_detAnchor[NBATCH * MAXDET];

// ---------------- pass 1: per-batch histogram of scores > CONF --------------
__global__ void k_hist(const float* __restrict__ test) {
    __shared__ float4 tile4[TILE_A * ROWF / 4];
    __shared__ unsigned int hh[HB];
    float* tile = (float*)tile4;
    const int b = blockIdx.y;
    const int tid = blockIdx.x;
    if (threadIdx.x < HB) hh[threadIdx.x] = 0u;
    const float4* src = (const float4*)(test + ((size_t)b * NA + (size_t)tid * TILE_A) * ROWF);
#pragma unroll
    for (int i = threadIdx.x; i < TILE_A * ROWF / 4; i += 256) tile4[i] = src[i];
    __syncthreads();
    for (int i = threadIdx.x; i < TILE_A * NCLS; i += 256) {
        int a = i / NCLS, c = i - a * NCLS;
        float v = tile[a * ROWF + 5 + c] * tile[a * ROWF + 4];
        if (v > CONF) {
            int bin = (int)(v * 256.0f); bin = bin > 255 ? 255 : bin;
            atomicAdd(&hh[bin], 1u);
        }
    }
    __syncthreads();
    if (threadIdx.x < HB && hh[threadIdx.x])
        atomicAdd(&g_hist[b * HB + threadIdx.x], hh[threadIdx.x]);
}

// ---------------- pass 2: compact candidates (thr computed inline) ----------
__global__ void k_compact(const float* __restrict__ test) {
    __shared__ float4 tile4[TILE_A * ROWF / 4];
    __shared__ int s_thr;
    float* tile = (float*)tile4;
    const int b   = blockIdx.y;
    const int tid = blockIdx.x;
    const int t   = threadIdx.x;

    if (t < 32) {
        int lane = t;
        unsigned h[8];
#pragma unroll
        for (int k = 0; k < 8; k++) h[k] = g_hist[b * HB + lane * 8 + k];
        unsigned tot = 0;
#pragma unroll
        for (int k = 0; k < 8; k++) tot += h[k];
        unsigned run = tot;
#pragma unroll
        for (int off = 1; off < 32; off <<= 1) {
            unsigned v = __shfl_down_sync(0xFFFFFFFFu, run, off);
            if (lane + off < 32) run += v;
        }
        unsigned above = run - tot;
        int cand = -1;
        unsigned cum = above;
        for (int k = 7; k >= 0; k--) {
            cum += h[k];
            if (cum >= TOPK) { cand = lane * 8 + k; break; }
        }
#pragma unroll
        for (int off = 16; off > 0; off >>= 1)
            cand = max(cand, __shfl_xor_sync(0xFFFFFFFFu, cand, off));
        if (lane == 0) s_thr = cand < 0 ? 0 : cand;
    }

    const float4* src = (const float4*)(test + ((size_t)b * NA + (size_t)tid * TILE_A) * ROWF);
#pragma unroll
    for (int i = t; i < TILE_A * ROWF / 4; i += 256) tile4[i] = src[i];
    __syncthreads();
    const int thr = s_thr;
    for (int i = t; i < TILE_A * NCLS; i += 256) {
        int a = i / NCLS, c = i - a * NCLS;
        float v = tile[a * ROWF + 5 + c] * tile[a * ROWF + 4];
        if (v > CONF) {
            int bin = (int)(v * 256.0f); bin = bin > 255 ? 255 : bin;
            if (bin >= thr) {
                int pos = atomicAdd(&g_candCnt[b], 1);
                if (pos < MAXC) {
                    unsigned flat = (unsigned)((tid * TILE_A + a) * NCLS + c);
                    g_candKey[b * MAXC + pos] =
                        ((unsigned long long)__float_as_uint(v) << 32) |
                        (unsigned long long)(0xFFFFFFFFu - flat);
                }
            }
        }
    }
}

// ---------------- hybrid bitonic helpers ------------------------------------
__device__ __forceinline__ unsigned long long cex_shfl(unsigned long long v, int i, int j, int k) {
    unsigned long long pv = __shfl_xor_sync(0xFFFFFFFFu, v, j);
    bool lower = ((i & j) == 0);
    bool desc  = ((i & k) == 0);
    return (desc == lower) ? (v > pv ? v : pv) : (v < pv ? v : pv);
}
__device__ __forceinline__ void cex_reg(unsigned long long& v0, unsigned long long& v1, int i0, int k) {
    bool desc = ((i0 & k) == 0);
    unsigned long long a = v0, b = v1;
    if (desc ? (a < b) : (a > b)) { v0 = b; v1 = a; }
}

// ---------------- sort (hybrid bitonic 2048) + greedy NMS, fused ------------
union SortU {
    unsigned long long s[MAXC];
    struct { int cls[TOPK]; int anc[TOPK]; } post;
};

__global__ void __launch_bounds__(1024, 1) k_sortnms(const float* __restrict__ test,
                                                     float* __restrict__ out) {
    __shared__ SortU u;
    __shared__ float sbx1[TOPK], sby1[TOPK], sbx2[TOPK], sby2[TOPK], sar[TOPK], sval[TOPK];
    __shared__ unsigned int vword[TOPK / 32];
    const int b = blockIdx.x;
    const int t = threadIdx.x;
    const int lane = t & 31, wid = t >> 5;
    const int base = wid * 64;
    const int i0 = base + lane, i1 = base + 32 + lane;

    int cnt = g_candCnt[b]; if (cnt > MAXC) cnt = MAXC;

    unsigned long long v0 = (i0 < cnt) ? g_candKey[b * MAXC + i0] : 0x00000000FFFFFFFFull;
    unsigned long long v1 = (i1 < cnt) ? g_candKey[b * MAXC + i1] : 0x00000000FFFFFFFFull;

#pragma unroll
    for (int k = 2; k <= 64; k <<= 1) {
#pragma unroll
        for (int j = k >> 1; j >= 1; j >>= 1) {
            if (j == 32) cex_reg(v0, v1, i0, k);
            else { v0 = cex_shfl(v0, i0, j, k); v1 = cex_shfl(v1, i1, j, k); }
        }
    }
    u.s[i0] = v0; u.s[i1] = v1;
    __syncthreads();

    for (int k = 128; k <= MAXC; k <<= 1) {
        for (int j = k >> 1; j >= 64; j >>= 1) {
#pragma unroll
            for (int i = t; i < MAXC; i += 1024) {
                int ixj = i ^ j;
                if (ixj > i) {
                    unsigned long long a = u.s[i], bb = u.s[ixj];
                    bool up = (i & k) == 0;
                    if (up ? (a < bb) : (a > bb)) { u.s[i] = bb; u.s[ixj] = a; }
                }
            }
            __syncthreads();
        }
        v0 = u.s[i0]; v1 = u.s[i1];
        cex_reg(v0, v1, i0, k);
#pragma unroll
        for (int j = 16; j >= 1; j >>= 1) {
            v0 = cex_shfl(v0, i0, j, k);
            v1 = cex_shfl(v1, i1, j, k);
        }
        u.s[i0] = v0; u.s[i1] = v1;
        __syncthreads();
    }

    unsigned long long key = u.s[t];
    __syncthreads();

    float v = __uint_as_float((unsigned)(key >> 32));
    unsigned flat = 0xFFFFFFFFu - (unsigned)(key & 0xFFFFFFFFull);
    bool valid = v > CONF;
    int anc = valid ? (int)(flat / NCLS) : 0;
    int cls = valid ? (int)(flat - (unsigned)anc * NCLS) : 0;

    const float* r = test + ((size_t)b * NA + anc) * ROWF;
    float cx = r[0], cy = r[1], w = r[2], h = r[3];
    float x1 = cx - 0.5f * w, y1 = cy - 0.5f * h;
    float x2 = cx + 0.5f * w, y2 = cy + 0.5f * h;
    sbx1[t] = x1; sby1[t] = y1; sbx2[t] = x2; sby2[t] = y2;
    sar[t] = fmaxf(x2 - x1, 0.f) * fmaxf(y2 - y1, 0.f);
    sval[t] = v; u.post.cls[t] = cls; u.post.anc[t] = anc;

    unsigned bal = __ballot_sync(0xFFFFFFFFu, valid);
    if (lane == 0) vword[wid] = bal;

    // zero scratch for next replay
    if (t < HB) g_hist[b * HB + t] = 0u;
    if (t == 0) g_candCnt[b] = 0;
    __syncthreads();

    for (int det = 0; det < MAXDET; det++) {
        unsigned m   = vword[lane];
        unsigned act = __ballot_sync(0xFFFFFFFFu, m != 0);
        int wsel = act ? (__ffs(act) - 1) : 0;
        unsigned mw = __shfl_sync(0xFFFFFFFFu, m, wsel);
        int j = act ? (wsel * 32 + __ffs(mw) - 1) : -1;

        if (t == 0) {
            size_t ob = (size_t)(b * MAXDET + det) * OUTROW;
            if (j >= 0) {
                out[ob + 0] = sbx1[j]; out[ob + 1] = sby1[j];
                out[ob + 2] = sbx2[j]; out[ob + 3] = sby2[j];
                out[ob + 4] = sval[j]; out[ob + 5] = (float)u.post.cls[j];
                g_detAnchor[b * MAXDET + det] = u.post.anc[j];
            } else {
                out[ob+0]=0.f; out[ob+1]=0.f; out[ob+2]=0.f;
                out[ob+3]=0.f; out[ob+4]=0.f; out[ob+5]=0.f;
                g_detAnchor[b * MAXDET + det] = 0;
            }
        }
        bool sup = false;
        if (j >= 0 && ((vword[wid] >> lane) & 1u)) {
            if (t == j) sup = true;
            else if (cls == u.post.cls[j]) {
                float lx = fmaxf(x1, sbx1[j]), ly = fmaxf(y1, sby1[j]);
                float rx = fminf(x2, sbx2[j]), ry = fminf(y2, sby2[j]);
                float iw = fmaxf(rx - lx, 0.f), ih = fmaxf(ry - ly, 0.f);
                float inter = iw * ih;
                float iou = inter / (sar[t] + sar[j] - inter + 1e-9f);
                sup = iou > IOUT;
            }
        }
        unsigned sm = __ballot_sync(0xFFFFFFFFu, sup);
        if (lane == 0) vword[wid] &= ~sm;
        __syncthreads();
    }
}

// ---------------- masks: float2 pair tables, no shfl in inner loop ----------
// dynamic smem layout (floats):
//  sA:0..980  patch:980..6260  sfx:6260..6420  swcx:6420..6580  spack:6580..6740
//  per-warp (470 each): rows2 (320 = float2[160]) + tw2 (150 = float2[75])
#define MSK_SMEM_FLOATS (6740 + 16 * 470)
#define MSK_SMEM_BYTES  (MSK_SMEM_FLOATS * 4)

__global__ void __launch_bounds__(512, 3) k_masks(const float* __restrict__ test,
                        const float* __restrict__ attn,
                        const float* __restrict__ bases,
                        const float* __restrict__ sem,
                        float* __restrict__ out) {
    extern __shared__ float dyn[];
    float* sA    = dyn;
    float* patch = dyn + 980;
    float* sfx   = dyn + 6260;
    float* swcx  = dyn + 6420;
    int*   spack = (int*)(dyn + 6580);
    const int b   = blockIdx.y;
    const int det = blockIdx.x;
    const int t   = threadIdx.x;
    const int lane = t & 31, wid = t >> 5;
    const int anc = g_detAnchor[b * MAXDET + det];

    float2* rows2 = (float2*)(dyn + 6740 + wid * 470);
    float2* tw2   = (float2*)(dyn + 6740 + wid * 470 + 320);

    const float* r = test + ((size_t)b * NA + anc) * ROWF;
    float cx = __ldg(r), cy = __ldg(r + 1), w = __ldg(r + 2), h = __ldg(r + 3);
    float bx1 = cx - 0.5f * w, by1 = cy - 0.5f * h;
    float bx2 = cx + 0.5f * w, by2 = cy + 0.5f * h;
    float X1 = bx1 * 0.25f - 0.5f, Y1 = by1 * 0.25f - 0.5f;
    float X2 = bx2 * 0.25f - 0.5f, Y2 = by2 * 0.25f - 0.5f;
    float DX = (X2 - X1) / (float)HW;
    float DY = (Y2 - Y1) / (float)HW;

    float sxa = X1 + 0.5f * DX;
    int x_lo  = (int)floorf(fminf(fmaxf(sxa, 0.f), 159.f));
    float sya = Y1 + 0.5f * DY;
    int y_lo  = (int)floorf(fminf(fmaxf(sya, 0.f), 159.f));

    if (t < HW) {
        int px = t;
        float sx = X1 + (px + 0.5f) * DX;
        bool  vx = (sx > -1.0f) && (sx < (float)HW);
        float cxc = fminf(fmaxf(sx, 0.0f), (float)(HW - 1));
        float fxl = floorf(cxc);
        int x0p = min(max((int)fxl - x_lo, 0), 31);
        sfx[px] = cxc - fxl;
        float txc = (px + 0.5f) * ((float)AR / (float)HW) - 0.5f;
        txc = fminf(fmaxf(txc, 0.0f), (float)(AR - 1));
        float ftx = floorf(txc);
        swcx[px] = txc - ftx;
        spack[px] = x0p | (((int)ftx) << 6) | (vx ? (1 << 11) : 0);
    }
    {
        const float4* ap = (const float4*)(attn + ((size_t)b * NA + anc) * ATTNF);
        for (int i = t; i < ATTNF / 4; i += 512) ((float4*)sA)[i] = ap[i];
    }
#pragma unroll
    for (int c = 0; c < 5; c++) {
        const float* F = (c < 4) ? bases + (size_t)(b * 4 + c) * (HW * HW)
                                 : sem + (size_t)b * (HW * HW);
        for (int i = t; i < 32 * 32; i += 512) {
            int yy = i >> 5, xx = i & 31;
            int gy = min(y_lo + yy, HW - 1);
            int gx = min(x_lo + xx, HW - 1);
            patch[(c * 32 + yy) * 33 + xx] = __ldg(F + gy * HW + gx);
        }
    }
    __syncthreads();

    const size_t obase = (size_t)(b * MAXDET + det) * OUTROW + 6;

    for (int py = wid; py < HW; py += 16) {
        float sy = Y1 + (py + 0.5f) * DY;
        bool  vy = (sy > -1.0f) && (sy < (float)HW);
        float cyc = fminf(fmaxf(sy, 0.0f), (float)(HW - 1));
        float fyl = floorf(cyc);
        int   y0p = min(max((int)fyl - y_lo, 0), 31);
        int   y1p = min(max(min((int)fyl + 1, HW - 1) - y_lo, 0), 31);
        float fy  = cyc - fyl;

#pragma unroll
        for (int c = 0; c < 5; c++) {
            float a0 = patch[(c * 32 + y0p) * 33 + lane];
            float a1 = patch[(c * 32 + y1p) * 33 + lane];
            float rv = fmaf(a1 - a0, fy, a0);
            float rn = __shfl_down_sync(0xFFFFFFFFu, rv, 1);
            rows2[c * 32 + lane] = make_float2(rv, rn);
        }

        float tyc = (py + 0.5f) * ((float)AR / (float)HW) - 0.5f;
        tyc = fminf(fmaxf(tyc, 0.0f), (float)(AR - 1));
        float fty = floorf(tyc);
        int cy0 = (int)fty, cy1 = min(cy0 + 1, AR - 1);
        float wy2 = tyc - fty;
        for (int i = lane; i < 75; i += 32) {
            int c = i / 15, k = i - c * 15;
            int ka = min(k, AR - 1), kb = min(k + 1, AR - 1);
            float a0 = sA[c * 196 + cy0 * AR + ka], a1 = sA[c * 196 + cy1 * AR + ka];
            float b0 = sA[c * 196 + cy0 * AR + kb], b1 = sA[c * 196 + cy1 * AR + kb];
            tw2[c * 15 + k] = make_float2(fmaf(a1 - a0, wy2, a0), fmaf(b1 - b0, wy2, b0));
        }
        __syncwarp();

#pragma unroll
        for (int sub = 0; sub < 5; sub++) {
            int px = sub * 32 + lane;
            int   pk  = spack[px];
            float fx  = sfx[px];
            float wcx = swcx[px];
            int x0p = pk & 63;
            int cx0 = (pk >> 6) & 31;
            bool vx = (pk >> 11) & 1;

            float esum = 0.f, acc = 0.f;
#pragma unroll
            for (int c = 0; c < 5; c++) {
                float2 tt = tw2[c * 15 + cx0];
                float e = __expf(fmaf(tt.y - tt.x, wcx, tt.x));
                esum += e;
                float2 rr = rows2[c * 32 + x0p];
                acc = fmaf(fmaf(rr.y - rr.x, fx, rr.x), e, acc);
            }
            acc = (vx && vy) ? acc : 0.f;
            float z = __fdividef(acc, esum);
            out[obase + (size_t)py * HW + px] = __fdividef(1.0f, 1.0f + __expf(-z));
        }
        __syncwarp();
    }
}

// ---------------- launch ----------------------------------------------------
extern "C" void kernel_launch(void* const* d_in, const int* in_sizes, int n_in,
                              void* d_out, int out_size) {
    const float *test = nullptr, *attn = nullptr, *bases = nullptr, *sem = nullptr;
    for (int i = 0; i < n_in; i++) {
        long long s = in_sizes[i];
        if      (s == (long long)NBATCH * NA * ROWF)   test  = (const float*)d_in[i];
        else if (s == (long long)NBATCH * NA * ATTNF)  attn  = (const float*)d_in[i];
        else if (s == (long long)NBATCH * 4 * HW * HW) bases = (const float*)d_in[i];
        else if (s == (long long)NBATCH * 1 * HW * HW) sem   = (const float*)d_in[i];
    }
    float* out = (float*)d_out;

    cudaFuncSetAttribute(k_masks, cudaFuncAttributeMaxDynamicSharedMemorySize, MSK_SMEM_BYTES);

    k_hist<<<dim3(NA / TILE_A, NBATCH), 256>>>(test);
    k_compact<<<dim3(NA / TILE_A, NBATCH), 256>>>(test);
    k_sortnms<<<NBATCH, 1024>>>(test, out);
    k_masks<<<dim3(MAXDET, NBATCH), 512, MSK_SMEM_BYTES>>>(test, attn, bases, sem, out);
}